// round 5
// baseline (speedup 1.0000x reference)
#include <cuda_runtime.h>

// ---------------------------------------------------------------------------
// GCN rewritten as:
//   agg1 = segment_sum(x[src], dst)                [N,128]  (CSR gather, no atomics)
//   hp   = relu(agg1 @ W1 + b1) @ W2               [N,64]   (fused MLP, 8x8 reg tiles)
//   out  = b2 + segment_sum(hp[src], dst)          [N,64]   (CSR gather)
// using segsum(h[src]) @ W == segsum((h@W)[src]).
// CSR (by dst) rebuilt per replay inside the captured graph.
// ---------------------------------------------------------------------------

#define NMAX 100000
#define EMAX 1600000
#define FULLMASK 0xFFFFFFFFu

__device__ __align__(16) float g_agg1[(size_t)NMAX * 128];
__device__ __align__(16) float g_hp[(size_t)NMAX * 64];
__device__ int g_counts[NMAX];
__device__ int g_rowptr[NMAX];
__device__ int g_cursor[NMAX];
__device__ int g_esrc[EMAX];
__device__ int g_blocksums[1024];

// ---------------- CSR build ----------------

__global__ void k_zero(int N) {
    int i = blockIdx.x * blockDim.x + threadIdx.x;
    if (i < N) g_counts[i] = 0;
}

__global__ void k_hist(const int* __restrict__ dst, int E) {
    int i = blockIdx.x * blockDim.x + threadIdx.x;
    if (i < E) atomicAdd(&g_counts[dst[i]], 1);
}

// shfl-based block scan: inclusive scan of 1024 values
__device__ __forceinline__ int block_scan_incl(int v, int tid) {
    __shared__ int ws[32];
    int lane = tid & 31, w = tid >> 5;
    int p = v;
    #pragma unroll
    for (int off = 1; off < 32; off <<= 1) {
        int t = __shfl_up_sync(FULLMASK, p, off);
        if (lane >= off) p += t;
    }
    if (lane == 31) ws[w] = p;
    __syncthreads();
    if (w == 0) {
        int s = ws[lane];
        #pragma unroll
        for (int off = 1; off < 32; off <<= 1) {
            int t = __shfl_up_sync(FULLMASK, s, off);
            if (lane >= off) s += t;
        }
        ws[lane] = s;
    }
    __syncthreads();
    int base = (w > 0) ? ws[w - 1] : 0;
    return base + p;
}

__global__ void k_scan1(int N) {
    int tid = threadIdx.x;
    int i = blockIdx.x * 1024 + tid;
    int v = (i < N) ? g_counts[i] : 0;
    int incl = block_scan_incl(v, tid);
    if (i < N) g_rowptr[i] = incl - v;               // exclusive within block
    if (tid == 1023) g_blocksums[blockIdx.x] = incl; // block total
}

__global__ void k_scan2(int nb) {
    int tid = threadIdx.x;
    int v = (tid < nb) ? g_blocksums[tid] : 0;
    int incl = block_scan_incl(v, tid);
    if (tid < nb) g_blocksums[tid] = incl - v;       // exclusive
}

__global__ void k_scan3(int N) {
    int i = blockIdx.x * blockDim.x + threadIdx.x;
    if (i < N) {
        int start = g_rowptr[i] + g_blocksums[i >> 10];
        g_rowptr[i] = start;
        g_cursor[i] = start;
    }
}

__global__ void k_fill(const int* __restrict__ src, const int* __restrict__ dst, int E) {
    int i = blockIdx.x * blockDim.x + threadIdx.x;
    if (i < E) {
        int d = dst[i];
        int p = atomicAdd(&g_cursor[d], 1);
        g_esrc[p] = src[i];
    }
}

// ---------------- layer-1 aggregation: warp per node, 128-wide ----------------

__global__ void k_agg1(const float* __restrict__ x, int N) {
    int gw = (blockIdx.x * blockDim.x + threadIdx.x) >> 5;
    int lane = threadIdx.x & 31;
    if (gw >= N) return;
    int beg = g_rowptr[gw];
    int cnt = g_counts[gw];
    float4 acc = make_float4(0.f, 0.f, 0.f, 0.f);
    for (int j = 0; j < cnt; j += 32) {
        int idx = 0;
        if (j + lane < cnt) idx = g_esrc[beg + j + lane];   // one coalesced load
        int m = min(32, cnt - j);
        int kk = 0;
        for (; kk + 4 <= m; kk += 4) {
            int s0 = __shfl_sync(FULLMASK, idx, kk);
            int s1 = __shfl_sync(FULLMASK, idx, kk + 1);
            int s2 = __shfl_sync(FULLMASK, idx, kk + 2);
            int s3 = __shfl_sync(FULLMASK, idx, kk + 3);
            float4 v0 = *(const float4*)(&x[(size_t)s0 * 128 + lane * 4]);
            float4 v1 = *(const float4*)(&x[(size_t)s1 * 128 + lane * 4]);
            float4 v2 = *(const float4*)(&x[(size_t)s2 * 128 + lane * 4]);
            float4 v3 = *(const float4*)(&x[(size_t)s3 * 128 + lane * 4]);
            acc.x += (v0.x + v1.x) + (v2.x + v3.x);
            acc.y += (v0.y + v1.y) + (v2.y + v3.y);
            acc.z += (v0.z + v1.z) + (v2.z + v3.z);
            acc.w += (v0.w + v1.w) + (v2.w + v3.w);
        }
        for (; kk < m; kk++) {
            int s0 = __shfl_sync(FULLMASK, idx, kk);
            float4 v0 = *(const float4*)(&x[(size_t)s0 * 128 + lane * 4]);
            acc.x += v0.x; acc.y += v0.y; acc.z += v0.z; acc.w += v0.w;
        }
    }
    *(float4*)(&g_agg1[(size_t)gw * 128 + lane * 4]) = acc;
}

// ---------------- fused MLP: hp = relu(agg1 @ W1 + b1) @ W2 ----------------
// BM=128 nodes per block, 256 threads.
// Phase 1: 128x128x128 GEMM, BK=16, 8x8 register tile (0.5 B/flop LDS).
//          As padded to 132 floats/row (k-major), Hs padded to 132/row.
// Phase 2: 128x64x128 off Hs, 8x4 tile with row = tr + i*16 mapping
//          (row stride 1 -> 132-word stride -> conflict-free broadcast loads).

#define AS_PITCH  132           // floats per k-row of As (pad 128+4)
#define HS_PITCH  132           // floats per row of Hs (pad 128+4)
#define AS_OFF    0
#define BS_OFF    (16 * AS_PITCH)                 // 2112 floats
#define HS_OFF    (BS_OFF + 16 * 128)             // 2112 + 2048 = 4160 floats
#define MLP_SMEM_FLOATS (HS_OFF + 128 * HS_PITCH) // 4160 + 16896 = 21056 floats
#define MLP_SMEM_BYTES  (MLP_SMEM_FLOATS * 4)     // 84224 bytes

__global__ __launch_bounds__(256, 2) void k_mlp(const float* __restrict__ W1,
                                                const float* __restrict__ b1,
                                                const float* __restrict__ W2,
                                                int N) {
    extern __shared__ float sm[];
    float* As  = sm + AS_OFF;   // [16][132] k-major
    float* Bs  = sm + BS_OFF;   // [16][128]
    float* W2s = sm;            // [32][64] phase 2, overlays As
    float* Hs  = sm + HS_OFF;   // [128][132]
    float4* Bs4  = (float4*)Bs;
    float4* W2s4 = (float4*)W2s;

    int t = threadIdx.x;
    int n0 = blockIdx.x * 128;
    int tr = t >> 4;   // 0..15
    int tc = t & 15;   // 0..15

    float acc[8][8];
    #pragma unroll
    for (int i = 0; i < 8; i++)
        #pragma unroll
        for (int j = 0; j < 8; j++) acc[i][j] = 0.f;

    #pragma unroll
    for (int kb = 0; kb < 8; kb++) {
        int k0 = kb * 16;
        // load As (transpose to [k][m], pitch 132) : 512 float4 source slots
        #pragma unroll
        for (int r = 0; r < 2; r++) {
            int slot = r * 256 + t;
            int m = slot >> 2;
            int kq = slot & 3;
            int row = n0 + m; if (row >= N) row = N - 1;
            float4 v = *(const float4*)(&g_agg1[(size_t)row * 128 + k0 + kq * 4]);
            As[(kq * 4 + 0) * AS_PITCH + m] = v.x;
            As[(kq * 4 + 1) * AS_PITCH + m] = v.y;
            As[(kq * 4 + 2) * AS_PITCH + m] = v.z;
            As[(kq * 4 + 3) * AS_PITCH + m] = v.w;
        }
        // load Bs [16][128] : direct copy
        #pragma unroll
        for (int r = 0; r < 2; r++) {
            int slot = r * 256 + t;
            int k = slot >> 5;
            int c4 = slot & 31;
            Bs4[k * 32 + c4] = *(const float4*)(&W1[(k0 + k) * 128 + c4 * 4]);
        }
        __syncthreads();
        #pragma unroll
        for (int k = 0; k < 16; k++) {
            float4 a0 = *(float4*)(&As[k * AS_PITCH + tr * 8]);
            float4 a1 = *(float4*)(&As[k * AS_PITCH + tr * 8 + 4]);
            float4 b0 = Bs4[k * 32 + tc * 2];
            float4 b1v = Bs4[k * 32 + tc * 2 + 1];
            float ar[8] = {a0.x, a0.y, a0.z, a0.w, a1.x, a1.y, a1.z, a1.w};
            float br[8] = {b0.x, b0.y, b0.z, b0.w, b1v.x, b1v.y, b1v.z, b1v.w};
            #pragma unroll
            for (int i = 0; i < 8; i++)
                #pragma unroll
                for (int j = 0; j < 8; j++)
                    acc[i][j] += ar[i] * br[j];
        }
        __syncthreads();
    }

    // bias + relu -> Hs (rows tr*8..+7, cols tc*8..+7), pitch 132
    {
        float4 bb0 = *(const float4*)(&b1[tc * 8]);
        float4 bb1 = *(const float4*)(&b1[tc * 8 + 4]);
        float bc[8] = {bb0.x, bb0.y, bb0.z, bb0.w, bb1.x, bb1.y, bb1.z, bb1.w};
        #pragma unroll
        for (int i = 0; i < 8; i++) {
            float4 h0, h1;
            h0.x = fmaxf(acc[i][0] + bc[0], 0.f);
            h0.y = fmaxf(acc[i][1] + bc[1], 0.f);
            h0.z = fmaxf(acc[i][2] + bc[2], 0.f);
            h0.w = fmaxf(acc[i][3] + bc[3], 0.f);
            h1.x = fmaxf(acc[i][4] + bc[4], 0.f);
            h1.y = fmaxf(acc[i][5] + bc[5], 0.f);
            h1.z = fmaxf(acc[i][6] + bc[6], 0.f);
            h1.w = fmaxf(acc[i][7] + bc[7], 0.f);
            *(float4*)(&Hs[(tr * 8 + i) * HS_PITCH + tc * 8])     = h0;
            *(float4*)(&Hs[(tr * 8 + i) * HS_PITCH + tc * 8 + 4]) = h1;
        }
    }
    __syncthreads();

    // phase 2: hp = Hs(128x128) @ W2(128x64), thread tile: rows tr + i*16, cols tc*4..+3
    float acc2[8][4];
    #pragma unroll
    for (int i = 0; i < 8; i++)
        #pragma unroll
        for (int j = 0; j < 4; j++) acc2[i][j] = 0.f;

    #pragma unroll
    for (int kb = 0; kb < 4; kb++) {
        int k0 = kb * 32;
        // load W2s [32][64]: 512 float4 slots, 2 per thread
        #pragma unroll
        for (int r = 0; r < 2; r++) {
            int slot = r * 256 + t;
            int k = slot >> 4;
            int c4 = slot & 15;
            W2s4[k * 16 + c4] = *(const float4*)(&W2[(k0 + k) * 64 + c4 * 4]);
        }
        __syncthreads();
        #pragma unroll
        for (int k = 0; k < 32; k += 4) {
            float4 hv[8];
            #pragma unroll
            for (int i = 0; i < 8; i++)
                hv[i] = *(float4*)(&Hs[(tr + i * 16) * HS_PITCH + k0 + k]);
            float4 bv[4];
            #pragma unroll
            for (int kk = 0; kk < 4; kk++)
                bv[kk] = W2s4[(k + kk) * 16 + tc];
            #pragma unroll
            for (int i = 0; i < 8; i++) {
                const float* hh = (const float*)&hv[i];
                #pragma unroll
                for (int kk = 0; kk < 4; kk++) {
                    acc2[i][0] += hh[kk] * bv[kk].x;
                    acc2[i][1] += hh[kk] * bv[kk].y;
                    acc2[i][2] += hh[kk] * bv[kk].z;
                    acc2[i][3] += hh[kk] * bv[kk].w;
                }
            }
        }
        __syncthreads();
    }

    #pragma unroll
    for (int i = 0; i < 8; i++) {
        int row = n0 + tr + i * 16;
        if (row < N) {
            float4 o = make_float4(acc2[i][0], acc2[i][1], acc2[i][2], acc2[i][3]);
            *(float4*)(&g_hp[(size_t)row * 64 + tc * 4]) = o;
        }
    }
}

// ---------------- layer-2 aggregation: warp per node, 64-wide, + b2 ----------------

__global__ void k_agg2(const float* __restrict__ b2, float* __restrict__ out, int N) {
    int gw = (blockIdx.x * blockDim.x + threadIdx.x) >> 5;
    int lane = threadIdx.x & 31;
    if (gw >= N) return;
    int beg = g_rowptr[gw];
    int cnt = g_counts[gw];
    float2 acc = *(const float2*)(&b2[lane * 2]);
    for (int j = 0; j < cnt; j += 32) {
        int idx = 0;
        if (j + lane < cnt) idx = g_esrc[beg + j + lane];
        int m = min(32, cnt - j);
        int kk = 0;
        for (; kk + 4 <= m; kk += 4) {
            int s0 = __shfl_sync(FULLMASK, idx, kk);
            int s1 = __shfl_sync(FULLMASK, idx, kk + 1);
            int s2 = __shfl_sync(FULLMASK, idx, kk + 2);
            int s3 = __shfl_sync(FULLMASK, idx, kk + 3);
            float2 v0 = *(const float2*)(&g_hp[(size_t)s0 * 64 + lane * 2]);
            float2 v1 = *(const float2*)(&g_hp[(size_t)s1 * 64 + lane * 2]);
            float2 v2 = *(const float2*)(&g_hp[(size_t)s2 * 64 + lane * 2]);
            float2 v3 = *(const float2*)(&g_hp[(size_t)s3 * 64 + lane * 2]);
            acc.x += (v0.x + v1.x) + (v2.x + v3.x);
            acc.y += (v0.y + v1.y) + (v2.y + v3.y);
        }
        for (; kk < m; kk++) {
            int s0 = __shfl_sync(FULLMASK, idx, kk);
            float2 v0 = *(const float2*)(&g_hp[(size_t)s0 * 64 + lane * 2]);
            acc.x += v0.x;
            acc.y += v0.y;
        }
    }
    *(float2*)(&out[(size_t)gw * 64 + lane * 2]) = acc;
}

// ---------------- launch ----------------

extern "C" void kernel_launch(void* const* d_in, const int* in_sizes, int n_in,
                              void* d_out, int out_size) {
    const float* x  = (const float*)d_in[0];
    const int* src  = (const int*)d_in[1];
    const int* dst  = (const int*)d_in[2];
    const float* W1 = (const float*)d_in[3];
    const float* b1 = (const float*)d_in[4];
    const float* W2 = (const float*)d_in[5];
    const float* b2 = (const float*)d_in[6];
    float* out = (float*)d_out;

    int N = in_sizes[0] / 128;
    int E = in_sizes[1];
    int nb = (N + 1023) / 1024;

    // unconditional (no static guards): idempotent, not a stream op, capture-safe
    cudaFuncSetAttribute(k_mlp, cudaFuncAttributeMaxDynamicSharedMemorySize, MLP_SMEM_BYTES);

    k_zero<<<(N + 255) / 256, 256>>>(N);
    k_hist<<<(E + 255) / 256, 256>>>(dst, E);
    k_scan1<<<nb, 1024>>>(N);
    k_scan2<<<1, 1024>>>(nb);
    k_scan3<<<(N + 255) / 256, 256>>>(N);
    k_fill<<<(E + 255) / 256, 256>>>(src, dst, E);

    int warp_blocks = (N * 32 + 255) / 256;      // warp per node
    k_agg1<<<warp_blocks, 256>>>(x, N);
    k_mlp<<<(N + 127) / 128, 256, MLP_SMEM_BYTES>>>(W1, b1, W2, N);
    k_agg2<<<warp_blocks, 256>>>(b2, out, N);
}

// round 8
// speedup vs baseline: 1.3561x; 1.3561x over previous
#include <cuda_runtime.h>
#include <cuda_bf16.h>
#include <cstdint>

// ---------------------------------------------------------------------------
// GCN:
//   agg1 = segment_sum(x[src], dst)               [N,128] CSR gather (no atomics)
//   hp   = relu(agg1 @ W1 + b1) @ W2              [N,64]  mma.sync bf16 3-MMA split
//   out  = b2 + segment_sum(hp[src], dst)         [N,64]  CSR gather
// using segsum(h[src]) @ W == segsum((h@W)[src]).
// ---------------------------------------------------------------------------

#define NMAX 100000
#define EMAX 1600000
#define FULLMASK 0xFFFFFFFFu

__device__ __align__(16) float g_agg1[(size_t)NMAX * 128];
__device__ __align__(16) float g_hp[(size_t)NMAX * 64];
__device__ int g_counts[NMAX];
__device__ int g_rowptr[NMAX];
__device__ int g_cursor[NMAX];
__device__ int g_esrc[EMAX];
__device__ int g_blocksums[1024];
// weight images: W^T, [n][k], pitch 136 bf16 (matches smem layout -> linear copies)
#define WPITCH 136
__device__ __align__(16) __nv_bfloat16 g_w1h[128 * WPITCH];
__device__ __align__(16) __nv_bfloat16 g_w1l[128 * WPITCH];
__device__ __align__(16) __nv_bfloat16 g_w2h[64 * WPITCH];
__device__ __align__(16) __nv_bfloat16 g_w2l[64 * WPITCH];

// pack two floats -> bf16x2 word (lower half = first arg)
__device__ __forceinline__ uint32_t pack_bf16x2(float lo, float hi) {
    uint32_t r;
    asm("cvt.rn.bf16x2.f32 %0, %1, %2;" : "=r"(r) : "f"(hi), "f"(lo));
    return r;
}

#define MMA_BF16(d, a0, a1, a2, a3, b0, b1) \
    asm volatile("mma.sync.aligned.m16n8k16.row.col.f32.bf16.bf16.f32 " \
        "{%0,%1,%2,%3}, {%4,%5,%6,%7}, {%8,%9}, {%0,%1,%2,%3};" \
        : "+f"((d)[0]), "+f"((d)[1]), "+f"((d)[2]), "+f"((d)[3]) \
        : "r"(a0), "r"(a1), "r"(a2), "r"(a3), "r"(b0), "r"(b1))

// ---------------- CSR build ----------------

__global__ void k_zero(int N) {
    int i = blockIdx.x * blockDim.x + threadIdx.x;
    if (i < N) g_counts[i] = 0;
}

__global__ void k_hist(const int* __restrict__ dst, int E) {
    int i = blockIdx.x * blockDim.x + threadIdx.x;
    if (i < E) atomicAdd(&g_counts[dst[i]], 1);
}

__global__ void k_scan1(int N) {
    __shared__ int s[1024];
    int tid = threadIdx.x;
    int i = blockIdx.x * 1024 + tid;
    int v = (i < N) ? g_counts[i] : 0;
    s[tid] = v;
    __syncthreads();
    #pragma unroll
    for (int off = 1; off < 1024; off <<= 1) {
        int t2 = 0;
        if (tid >= off) t2 = s[tid - off];
        __syncthreads();
        if (tid >= off) s[tid] += t2;
        __syncthreads();
    }
    if (i < N) g_rowptr[i] = s[tid] - v;
    if (tid == 1023) g_blocksums[blockIdx.x] = s[tid];
}

__global__ void k_scan2(int nb) {
    __shared__ int s[1024];
    int tid = threadIdx.x;
    int v = (tid < nb) ? g_blocksums[tid] : 0;
    s[tid] = v;
    __syncthreads();
    #pragma unroll
    for (int off = 1; off < 1024; off <<= 1) {
        int t2 = 0;
        if (tid >= off) t2 = s[tid - off];
        __syncthreads();
        if (tid >= off) s[tid] += t2;
        __syncthreads();
    }
    if (tid < nb) g_blocksums[tid] = s[tid] - v;
}

__global__ void k_scan3(int N) {
    int i = blockIdx.x * blockDim.x + threadIdx.x;
    if (i < N) {
        int start = g_rowptr[i] + g_blocksums[i >> 10];
        g_rowptr[i] = start;
        g_cursor[i] = start;
    }
}

__global__ void k_fill(const int* __restrict__ src, const int* __restrict__ dst, int E) {
    int i = blockIdx.x * blockDim.x + threadIdx.x;
    if (i < E) {
        int d = dst[i];
        int p = atomicAdd(&g_cursor[d], 1);
        g_esrc[p] = src[i];
    }
}

// ---------------- layer-1 aggregation: warp per node, 128-wide ----------------

__global__ void k_agg1(const float* __restrict__ x, int N) {
    int gw = (blockIdx.x * blockDim.x + threadIdx.x) >> 5;
    int lane = threadIdx.x & 31;
    if (gw >= N) return;
    int beg = g_rowptr[gw];
    int cnt = g_counts[gw];
    float4 acc = make_float4(0.f, 0.f, 0.f, 0.f);
    int j = 0;
    for (; j + 4 <= cnt; j += 4) {
        int s0 = g_esrc[beg + j];
        int s1 = g_esrc[beg + j + 1];
        int s2 = g_esrc[beg + j + 2];
        int s3 = g_esrc[beg + j + 3];
        float4 v0 = *(const float4*)(&x[(size_t)s0 * 128 + lane * 4]);
        float4 v1 = *(const float4*)(&x[(size_t)s1 * 128 + lane * 4]);
        float4 v2 = *(const float4*)(&x[(size_t)s2 * 128 + lane * 4]);
        float4 v3 = *(const float4*)(&x[(size_t)s3 * 128 + lane * 4]);
        acc.x += (v0.x + v1.x) + (v2.x + v3.x);
        acc.y += (v0.y + v1.y) + (v2.y + v3.y);
        acc.z += (v0.z + v1.z) + (v2.z + v3.z);
        acc.w += (v0.w + v1.w) + (v2.w + v3.w);
    }
    for (; j < cnt; j++) {
        int s0 = g_esrc[beg + j];
        float4 v0 = *(const float4*)(&x[(size_t)s0 * 128 + lane * 4]);
        acc.x += v0.x; acc.y += v0.y; acc.z += v0.z; acc.w += v0.w;
    }
    *(float4*)(&g_agg1[(size_t)gw * 128 + lane * 4]) = acc;
}

// ---------------- weight split/transpose (once per replay) ----------------
// B images = W^T : image[n][k] = W[k][n], split into bf16 hi + lo, pitch 136.

__global__ void k_wsplit(const float* __restrict__ W1, const float* __restrict__ W2) {
    int i = blockIdx.x * blockDim.x + threadIdx.x;
    if (i < 16384) {
        int n = i >> 7, k = i & 127;           // W1: [128][128]
        float v = W1[k * 128 + n];
        __nv_bfloat16 hb = __float2bfloat16(v);
        __nv_bfloat16 lb = __float2bfloat16(v - __bfloat162float(hb));
        g_w1h[n * WPITCH + k] = hb;
        g_w1l[n * WPITCH + k] = lb;
    } else if (i < 24576) {
        int j = i - 16384;
        int n = j >> 7, k = j & 127;           // W2: [128][64]
        float v = W2[k * 64 + n];
        __nv_bfloat16 hb = __float2bfloat16(v);
        __nv_bfloat16 lb = __float2bfloat16(v - __bfloat162float(hb));
        g_w2h[n * WPITCH + k] = hb;
        g_w2l[n * WPITCH + k] = lb;
    }
}

// ---------------- HMMA MLP: hp = relu(agg1@W1+b1)@W2 ----------------
// 256 threads (8 warps), BM=128 rows/block; warp w owns rows w*16..+15.
// smem pitch = 68 words (136 bf16): A/B fragments are single conflict-free LDS.b32.
// 3-MMA split per k-step: D += Ah*Bh + Ah*Bl + Al*Bh (fp32 accum).

#define PW 68                         // pitch in 32-bit words
#define SM_BIAS 0                     // 128 floats = 512 B
#define SM_AH   512                   // 128*68*4 = 34816
#define SM_AL   (SM_AH + 34816)
#define SM_W1H  (SM_AL + 34816)
#define SM_W1L  (SM_W1H + 34816)
#define SM_W2H  (SM_W1L + 34816)      // 64*68*4 = 17408
#define SM_W2L  (SM_W2H + 17408)
#define SM_TOT  (SM_W2L + 17408)      // 174592 bytes

__global__ __launch_bounds__(256) void k_mlp(const float* __restrict__ b1, int N) {
    extern __shared__ char sm[];
    float* bias = (float*)(sm + SM_BIAS);
    uint32_t* Ah = (uint32_t*)(sm + SM_AH);
    uint32_t* Al = (uint32_t*)(sm + SM_AL);
    const uint32_t* B1h = (const uint32_t*)(sm + SM_W1H);
    const uint32_t* B1l = (const uint32_t*)(sm + SM_W1L);
    const uint32_t* B2h = (const uint32_t*)(sm + SM_W2H);
    const uint32_t* B2l = (const uint32_t*)(sm + SM_W2L);

    int t = threadIdx.x;
    int n0 = blockIdx.x * 128;

    // --- stage weights (linear uint4 copies of pre-built images) ---
    {
        uint4* d;
        const uint4* s;
        d = (uint4*)(sm + SM_W1H); s = (const uint4*)g_w1h;
        for (int i = t; i < 2176; i += 256) d[i] = s[i];
        d = (uint4*)(sm + SM_W1L); s = (const uint4*)g_w1l;
        for (int i = t; i < 2176; i += 256) d[i] = s[i];
        d = (uint4*)(sm + SM_W2H); s = (const uint4*)g_w2h;
        for (int i = t; i < 1088; i += 256) d[i] = s[i];
        d = (uint4*)(sm + SM_W2L); s = (const uint4*)g_w2l;
        for (int i = t; i < 1088; i += 256) d[i] = s[i];
        if (t < 128) bias[t] = b1[t];
    }
    // --- stage A: load agg1 rows, split fp32 -> bf16 hi/lo ---
    {
        int row = t >> 1;
        int seg = t & 1;                       // half-row (64 cols)
        int rowc = n0 + row; if (rowc >= N) rowc = N - 1;
        const float* xr = &g_agg1[(size_t)rowc * 128 + seg * 64];
        #pragma unroll
        for (int q = 0; q < 16; q++) {
            float4 v = *(const float4*)(xr + q * 4);
            __nv_bfloat16 h0 = __float2bfloat16(v.x), h1 = __float2bfloat16(v.y);
            __nv_bfloat16 h2 = __float2bfloat16(v.z), h3 = __float2bfloat16(v.w);
            __nv_bfloat162 p0(h0, h1), p1(h2, h3);
            int wbase = row * PW + seg * 32 + q * 2;
            Ah[wbase]     = *(uint32_t*)&p0;
            Ah[wbase + 1] = *(uint32_t*)&p1;
            Al[wbase]     = pack_bf16x2(v.x - __bfloat162float(h0), v.y - __bfloat162float(h1));
            Al[wbase + 1] = pack_bf16x2(v.z - __bfloat162float(h2), v.w - __bfloat162float(h3));
        }
    }
    __syncthreads();

    int lane = t & 31, w = t >> 5;
    int g = lane >> 2, tig = lane & 3;
    int r0 = w * 16;                   // this warp's rows (block-local)

    // ---------------- layer 1: 16x128 per warp ----------------
    float acc[16][4];
    #pragma unroll
    for (int nt = 0; nt < 16; nt++)
        #pragma unroll
        for (int q = 0; q < 4; q++) acc[nt][q] = 0.f;

    #pragma unroll
    for (int kt = 0; kt < 8; kt++) {
        int ka = kt * 8 + tig;
        uint32_t ah0 = Ah[(r0 + g) * PW + ka];
        uint32_t ah1 = Ah[(r0 + g + 8) * PW + ka];
        uint32_t ah2 = Ah[(r0 + g) * PW + ka + 4];
        uint32_t ah3 = Ah[(r0 + g + 8) * PW + ka + 4];
        uint32_t al0 = Al[(r0 + g) * PW + ka];
        uint32_t al1 = Al[(r0 + g + 8) * PW + ka];
        uint32_t al2 = Al[(r0 + g) * PW + ka + 4];
        uint32_t al3 = Al[(r0 + g + 8) * PW + ka + 4];
        #pragma unroll
        for (int nt = 0; nt < 16; nt++) {
            int bo = (nt * 8 + g) * PW + ka;
            uint32_t bh0 = B1h[bo], bh1 = B1h[bo + 4];
            uint32_t bl0 = B1l[bo], bl1 = B1l[bo + 4];
            MMA_BF16(acc[nt], ah0, ah1, ah2, ah3, bh0, bh1);
            MMA_BF16(acc[nt], ah0, ah1, ah2, ah3, bl0, bl1);
            MMA_BF16(acc[nt], al0, al1, al2, al3, bh0, bh1);
        }
    }

    // epilogue 1: bias + relu + bf16 split -> H (reuse Ah/Al; warp-private rows)
    #pragma unroll
    for (int nt = 0; nt < 16; nt++) {
        int c0 = nt * 8 + tig * 2;
        float bx = bias[c0], by = bias[c0 + 1];
        float f0 = fmaxf(acc[nt][0] + bx, 0.f);
        float f1 = fmaxf(acc[nt][1] + by, 0.f);
        float f2 = fmaxf(acc[nt][2] + bx, 0.f);
        float f3 = fmaxf(acc[nt][3] + by, 0.f);
        __nv_bfloat16 h0 = __float2bfloat16(f0), h1 = __float2bfloat16(f1);
        __nv_bfloat16 h2 = __float2bfloat16(f2), h3 = __float2bfloat16(f3);
        __nv_bfloat162 p0(h0, h1), p1(h2, h3);
        int w0 = (r0 + g) * PW + nt * 4 + tig;
        int w1 = (r0 + g + 8) * PW + nt * 4 + tig;
        Ah[w0] = *(uint32_t*)&p0;
        Ah[w1] = *(uint32_t*)&p1;
        Al[w0] = pack_bf16x2(f0 - __bfloat162float(h0), f1 - __bfloat162float(h1));
        Al[w1] = pack_bf16x2(f2 - __bfloat162float(h2), f3 - __bfloat162float(h3));
    }
    __syncwarp();

    // ---------------- layer 2: 16x64 per warp ----------------
    float acc2[8][4];
    #pragma unroll
    for (int nt = 0; nt < 8; nt++)
        #pragma unroll
        for (int q = 0; q < 4; q++) acc2[nt][q] = 0.f;

    #pragma unroll
    for (int kt = 0; kt < 8; kt++) {
        int ka = kt * 8 + tig;
        uint32_t ah0 = Ah[(r0 + g) * PW + ka];
        uint32_t ah1 = Ah[(r0 + g + 8) * PW + ka];
        uint32_t ah2 = Ah[(r0 + g) * PW + ka + 4];
        uint32_t ah3 = Ah[(r0 + g + 8) * PW + ka + 4];
        uint32_t al0 = Al[(r0 + g) * PW + ka];
        uint32_t al1 = Al[(r0 + g + 8) * PW + ka];
        uint32_t al2 = Al[(r0 + g) * PW + ka + 4];
        uint32_t al3 = Al[(r0 + g + 8) * PW + ka + 4];
        #pragma unroll
        for (int nt = 0; nt < 8; nt++) {
            int bo = (nt * 8 + g) * PW + ka;
            uint32_t bh0 = B2h[bo], bh1 = B2h[bo + 4];
            uint32_t bl0 = B2l[bo], bl1 = B2l[bo + 4];
            MMA_BF16(acc2[nt], ah0, ah1, ah2, ah3, bh0, bh1);
            MMA_BF16(acc2[nt], ah0, ah1, ah2, ah3, bl0, bl1);
            MMA_BF16(acc2[nt], al0, al1, al2, al3, bh0, bh1);
        }
    }

    // final store: hp rows
    int row0 = n0 + r0 + g;
    int row1 = row0 + 8;
    #pragma unroll
    for (int nt = 0; nt < 8; nt++) {
        int c0 = nt * 8 + tig * 2;
        if (row0 < N)
            *(float2*)(&g_hp[(size_t)row0 * 64 + c0]) = make_float2(acc2[nt][0], acc2[nt][1]);
        if (row1 < N)
            *(float2*)(&g_hp[(size_t)row1 * 64 + c0]) = make_float2(acc2[nt][2], acc2[nt][3]);
    }
}

// ---------------- layer-2 aggregation: warp per node, 64-wide, + b2 ----------------

__global__ void k_agg2(const float* __restrict__ b2, float* __restrict__ out, int N) {
    int gw = (blockIdx.x * blockDim.x + threadIdx.x) >> 5;
    int lane = threadIdx.x & 31;
    if (gw >= N) return;
    int beg = g_rowptr[gw];
    int cnt = g_counts[gw];
    float2 acc = *(const float2*)(&b2[lane * 2]);
    int j = 0;
    for (; j + 4 <= cnt; j += 4) {
        int s0 = g_esrc[beg + j];
        int s1 = g_esrc[beg + j + 1];
        int s2 = g_esrc[beg + j + 2];
        int s3 = g_esrc[beg + j + 3];
        float2 v0 = *(const float2*)(&g_hp[(size_t)s0 * 64 + lane * 2]);
        float2 v1 = *(const float2*)(&g_hp[(size_t)s1 * 64 + lane * 2]);
        float2 v2 = *(const float2*)(&g_hp[(size_t)s2 * 64 + lane * 2]);
        float2 v3 = *(const float2*)(&g_hp[(size_t)s3 * 64 + lane * 2]);
        acc.x += (v0.x + v1.x) + (v2.x + v3.x);
        acc.y += (v0.y + v1.y) + (v2.y + v3.y);
    }
    for (; j < cnt; j++) {
        int s0 = g_esrc[beg + j];
        float2 v0 = *(const float2*)(&g_hp[(size_t)s0 * 64 + lane * 2]);
        acc.x += v0.x;
        acc.y += v0.y;
    }
    *(float2*)(&out[(size_t)gw * 64 + lane * 2]) = acc;
}

// ---------------- launch ----------------

extern "C" void kernel_launch(void* const* d_in, const int* in_sizes, int n_in,
                              void* d_out, int out_size) {
    const float* x  = (const float*)d_in[0];
    const int* src  = (const int*)d_in[1];
    const int* dst  = (const int*)d_in[2];
    const float* W1 = (const float*)d_in[3];
    const float* b1 = (const float*)d_in[4];
    const float* W2 = (const float*)d_in[5];
    const float* b2 = (const float*)d_in[6];
    float* out = (float*)d_out;

    int N = in_sizes[0] / 128;
    int E = in_sizes[1];
    int nb = (N + 1023) / 1024;

    cudaFuncSetAttribute(k_mlp, cudaFuncAttributeMaxDynamicSharedMemorySize, SM_TOT);

    k_zero<<<(N + 255) / 256, 256>>>(N);
    k_hist<<<(E + 255) / 256, 256>>>(dst, E);
    k_scan1<<<nb, 1024>>>(N);
    k_scan2<<<1, 1024>>>(nb);
    k_scan3<<<(N + 255) / 256, 256>>>(N);
    k_fill<<<(E + 255) / 256, 256>>>(src, dst, E);
    k_wsplit<<<96, 256>>>(W1, W2);

    int warp_blocks = (N * 32 + 255) / 256;      // warp per node
    k_agg1<<<warp_blocks, 256>>>(x, N);
    k_mlp<<<(N + 127) / 128, 256, SM_TOT>>>(b1, N);
    k_agg2<<<warp_blocks, 256>>>(b2, out, N);
}